// round 16
// baseline (speedup 1.0000x reference)
#include <cuda_runtime.h>
#include <cuda_bf16.h>

// ---------------------------------------------------------------------------
// GNN_23630910062676: 2-layer GCN, pull-based aggregation via CSR.
//   degi histogram (with tickets) -> single-kernel lookback scan -> fill
//   AX[n] = dinv[n]*(dinv[n]*x[n] + sum_s dinv[s]*x[s])
//   H = relu(AX @ W1 + b1) ; G = H @ W2
//   out[n] = b2 + dinv[n]*(dinv[n]*G[n] + sum_s dinv[s]*G[s])
// R16: decoupled-lookback scan fuses scan1+scan3 into one launch;
//      count/fill reverted to R14 2-way (best measured).
// ---------------------------------------------------------------------------

#define N_NODES 50000
#define N_EDGES 800000
#define DIN  64
#define DHID 128
#define DOUT 64

#define SCAN_BS 512
#define SCAN_NB ((N_NODES + SCAN_BS - 1) / SCAN_BS)   // 98 blocks (< 148 SMs)

__device__ int   g_degi[N_NODES];
__device__ int   g_off [N_NODES + 1];
__device__ int   g_bsum[SCAN_NB];        // -1 = not ready (memset 0xFF)
__device__ int   g_tick[N_EDGES];
__device__ int   g_col [N_EDGES];
__device__ float g_dinv[N_NODES];
__device__ float g_AX  [N_NODES * DIN];
__device__ float g_H   [N_NODES * DHID];
__device__ float g_G   [N_NODES * DOUT];

// ---------------------------------------------------------------------------
// Histogram + tickets, 2 edges per thread (R14-proven form).
__global__ void k_count(const int* __restrict__ dst) {
    int e = blockIdx.x * blockDim.x + threadIdx.x;
    int e2 = e + (N_EDGES / 2);
    if (e < N_EDGES / 2) {
        g_tick[e]  = atomicAdd(&g_degi[dst[e]], 1);
        g_tick[e2] = atomicAdd(&g_degi[dst[e2]], 1);
    }
}

// ---------------------------------------------------------------------------
// Single-kernel exclusive scan with decoupled lookback.
// 98 blocks x 512 threads; all blocks resident -> lookback cannot deadlock.
__global__ void __launch_bounds__(SCAN_BS) k_scan() {
    int gid  = blockIdx.x * SCAN_BS + threadIdx.x;
    int lane = threadIdx.x & 31;
    int wid  = threadIdx.x >> 5;

    int v = (gid < N_NODES) ? g_degi[gid] : 0;

    // warp-inclusive scan
    int xi = v;
    #pragma unroll
    for (int off = 1; off < 32; off <<= 1) {
        int y = __shfl_up_sync(0xFFFFFFFFu, xi, off);
        if (lane >= off) xi += y;
    }

    __shared__ int wpre[16];
    if (lane == 31) wpre[wid] = xi;
    __syncthreads();
    if (wid == 0 && lane < 16) {
        int s = wpre[lane];
        #pragma unroll
        for (int off = 1; off < 16; off <<= 1) {
            int y = __shfl_up_sync(0xFFFFu, s, off);
            if (lane >= off) s += y;
        }
        wpre[lane] = s;   // inclusive warp-sum prefix
    }
    __syncthreads();

    int blockIncl = wpre[15];
    int myExcl = (xi - v) + (wid > 0 ? wpre[wid - 1] : 0);

    // publish this block's aggregate (g_bsum pre-set to -1)
    if (threadIdx.x == 0) atomicExch(&g_bsum[blockIdx.x], blockIncl);

    // lookback: warp 0 sums all predecessor aggregates (spin until published)
    __shared__ int s_prefix;
    if (wid == 0) {
        int total = 0;
        for (int base = 0; base < blockIdx.x; base += 32) {
            int idx = base + lane;
            int val = 0;
            if (idx < blockIdx.x) {
                do { val = atomicAdd(&g_bsum[idx], 0); } while (val < 0);
            }
            #pragma unroll
            for (int off = 16; off >= 1; off >>= 1)
                val += __shfl_down_sync(0xFFFFFFFFu, val, off);
            if (lane == 0) total += val;
        }
        if (lane == 0) s_prefix = total;
    }
    __syncthreads();
    int prefix = s_prefix;

    if (gid < N_NODES) {
        g_off[gid]  = myExcl + prefix;
        g_dinv[gid] = rsqrtf((float)(v + 1));
    }
    if (gid == N_NODES) g_off[N_NODES] = N_EDGES;
}

// Atomic-free fill using tickets, 2 edges per thread (R14-proven form).
__global__ void k_fill(const int* __restrict__ src, const int* __restrict__ dst) {
    int e = blockIdx.x * blockDim.x + threadIdx.x;
    int e2 = e + (N_EDGES / 2);
    if (e < N_EDGES / 2) {
        g_col[g_off[dst[e]]  + g_tick[e]]  = src[e];
        g_col[g_off[dst[e2]] + g_tick[e2]] = src[e2];
    }
}

// ---------------------------------------------------------------------------
// Pull aggregation over a 64-wide tensor: ONE WARP per node, float2 per lane.
#define AGG_BODY(SRC2, EPILOGUE)                                                \
    int n = blockIdx.x * 8 + (threadIdx.x >> 5);                                \
    if (n >= N_NODES) return;                                                   \
    int l = threadIdx.x & 31;                                                   \
    float dn = g_dinv[n];                                                       \
    float2 v = SRC2[(size_t)n * 32 + l];                                        \
    float ax = v.x * dn, ay = v.y * dn;                                         \
    int e = g_off[n], end = g_off[n + 1];                                       \
    for (; e + 4 <= end; e += 4) {                                              \
        int s0 = g_col[e], s1 = g_col[e + 1], s2 = g_col[e + 2], s3 = g_col[e + 3]; \
        float d0 = g_dinv[s0], d1 = g_dinv[s1], d2 = g_dinv[s2], d3 = g_dinv[s3];   \
        float2 u0 = SRC2[(size_t)s0 * 32 + l];                                  \
        float2 u1 = SRC2[(size_t)s1 * 32 + l];                                  \
        float2 u2 = SRC2[(size_t)s2 * 32 + l];                                  \
        float2 u3 = SRC2[(size_t)s3 * 32 + l];                                  \
        ax = fmaf(u0.x, d0, ax); ay = fmaf(u0.y, d0, ay);                       \
        ax = fmaf(u1.x, d1, ax); ay = fmaf(u1.y, d1, ay);                       \
        ax = fmaf(u2.x, d2, ax); ay = fmaf(u2.y, d2, ay);                       \
        ax = fmaf(u3.x, d3, ax); ay = fmaf(u3.y, d3, ay);                       \
    }                                                                           \
    for (; e < end; e++) {                                                      \
        int s = g_col[e];                                                       \
        float ds = g_dinv[s];                                                   \
        float2 u = SRC2[(size_t)s * 32 + l];                                    \
        ax = fmaf(u.x, ds, ax); ay = fmaf(u.y, ds, ay);                         \
    }                                                                           \
    EPILOGUE

__global__ void __launch_bounds__(256) k_aggX(const float* __restrict__ x) {
    const float2* SRC2 = reinterpret_cast<const float2*>(x);
    AGG_BODY(SRC2,
             {
                 float2 o = make_float2(ax * dn, ay * dn);
                 reinterpret_cast<float2*>(g_AX)[(size_t)n * 32 + l] = o;
             })
}

__global__ void __launch_bounds__(256) k_agg2(const float* __restrict__ b2,
                                              float* __restrict__ out) {
    const float2* SRC2 = reinterpret_cast<const float2*>(g_G);
    AGG_BODY(SRC2,
             {
                 float2 bb = reinterpret_cast<const float2*>(b2)[l];
                 float2 o = make_float2(fmaf(ax, dn, bb.x), fmaf(ay, dn, bb.y));
                 reinterpret_cast<float2*>(out)[(size_t)n * 32 + l] = o;
             })
}

// ---------------------------------------------------------------------------
// GEMM1: H[N,128] = relu(AX[N,64] @ W1[64,128] + b1)
// Block: 128 rows x 128 cols, 256 threads, 8x8 register tile each.
__global__ void __launch_bounds__(256) k_gemm1(const float* __restrict__ W1,
                                               const float* __restrict__ b1) {
    __shared__ float sA[DIN * 128];   // [k][row] 32 KB
    __shared__ float sB[DIN * DHID];  // [k][col] 32 KB
    int t = threadIdx.x;
    int row0 = blockIdx.x * 128;

    for (int i = t; i < DIN * DHID; i += 256) sB[i] = W1[i];
    for (int i = t; i < 128 * 16; i += 256) {
        int r = i >> 4, kq = i & 15;
        float4 v = make_float4(0.f, 0.f, 0.f, 0.f);
        if (row0 + r < N_NODES)
            v = reinterpret_cast<const float4*>(g_AX + (size_t)(row0 + r) * DIN)[kq];
        sA[(kq * 4 + 0) * 128 + r] = v.x;
        sA[(kq * 4 + 1) * 128 + r] = v.y;
        sA[(kq * 4 + 2) * 128 + r] = v.z;
        sA[(kq * 4 + 3) * 128 + r] = v.w;
    }
    __syncthreads();

    int tc = t & 15, tr = t >> 4;
    int c0 = tc * 8, r0 = tr * 8;
    float acc[8][8];
    #pragma unroll
    for (int r = 0; r < 8; r++)
        #pragma unroll
        for (int c = 0; c < 8; c++) acc[r][c] = 0.f;

    #pragma unroll 4
    for (int k = 0; k < DIN; k++) {
        float4 a0 = *reinterpret_cast<float4*>(&sA[k * 128 + r0]);
        float4 a1 = *reinterpret_cast<float4*>(&sA[k * 128 + r0 + 4]);
        float4 q0 = *reinterpret_cast<float4*>(&sB[k * DHID + c0]);
        float4 q1 = *reinterpret_cast<float4*>(&sB[k * DHID + c0 + 4]);
        float a[8] = {a0.x, a0.y, a0.z, a0.w, a1.x, a1.y, a1.z, a1.w};
        float b[8] = {q0.x, q0.y, q0.z, q0.w, q1.x, q1.y, q1.z, q1.w};
        #pragma unroll
        for (int r = 0; r < 8; r++)
            #pragma unroll
            for (int c = 0; c < 8; c++) acc[r][c] = fmaf(a[r], b[c], acc[r][c]);
    }

    float bias[8];
    #pragma unroll
    for (int c = 0; c < 8; c++) bias[c] = __ldg(&b1[c0 + c]);

    #pragma unroll
    for (int r = 0; r < 8; r++) {
        int grow = row0 + r0 + r;
        if (grow >= N_NODES) break;
        float4 o0, o1;
        o0.x = fmaxf(acc[r][0] + bias[0], 0.f);
        o0.y = fmaxf(acc[r][1] + bias[1], 0.f);
        o0.z = fmaxf(acc[r][2] + bias[2], 0.f);
        o0.w = fmaxf(acc[r][3] + bias[3], 0.f);
        o1.x = fmaxf(acc[r][4] + bias[4], 0.f);
        o1.y = fmaxf(acc[r][5] + bias[5], 0.f);
        o1.z = fmaxf(acc[r][6] + bias[6], 0.f);
        o1.w = fmaxf(acc[r][7] + bias[7], 0.f);
        float* dstp = g_H + (size_t)grow * DHID + c0;
        reinterpret_cast<float4*>(dstp)[0] = o0;
        reinterpret_cast<float4*>(dstp)[1] = o1;
    }
}

// ---------------------------------------------------------------------------
// GEMM2: G[N,64] = H[N,128] @ W2[128,64]
// Block: 128 rows x 64 cols, 256 threads, 8x4 tile, K in two 64-chunks.
__global__ void __launch_bounds__(256) k_gemm2(const float* __restrict__ W2) {
    __shared__ float sA[64 * 128];    // [k-chunk][row] 32 KB
    __shared__ float sB[DHID * DOUT]; // [k][col] 32 KB
    int t = threadIdx.x;
    int row0 = blockIdx.x * 128;

    for (int i = t; i < DHID * DOUT; i += 256) sB[i] = W2[i];

    int tc = t & 15, tr = t >> 4;
    int c0 = tc * 4, r0 = tr * 8;
    float acc[8][4];
    #pragma unroll
    for (int r = 0; r < 8; r++)
        #pragma unroll
        for (int c = 0; c < 4; c++) acc[r][c] = 0.f;

    #pragma unroll
    for (int ch = 0; ch < 2; ch++) {
        __syncthreads();
        for (int i = t; i < 128 * 16; i += 256) {
            int r = i >> 4, kq = i & 15;
            float4 v = make_float4(0.f, 0.f, 0.f, 0.f);
            if (row0 + r < N_NODES)
                v = reinterpret_cast<const float4*>(g_H + (size_t)(row0 + r) * DHID)
                        [ch * 16 + kq];
            sA[(kq * 4 + 0) * 128 + r] = v.x;
            sA[(kq * 4 + 1) * 128 + r] = v.y;
            sA[(kq * 4 + 2) * 128 + r] = v.z;
            sA[(kq * 4 + 3) * 128 + r] = v.w;
        }
        __syncthreads();

        #pragma unroll 4
        for (int k = 0; k < 64; k++) {
            float4 a0 = *reinterpret_cast<float4*>(&sA[k * 128 + r0]);
            float4 a1 = *reinterpret_cast<float4*>(&sA[k * 128 + r0 + 4]);
            float4 q0 = *reinterpret_cast<float4*>(&sB[(ch * 64 + k) * DOUT + c0]);
            float a[8] = {a0.x, a0.y, a0.z, a0.w, a1.x, a1.y, a1.z, a1.w};
            float b[4] = {q0.x, q0.y, q0.z, q0.w};
            #pragma unroll
            for (int r = 0; r < 8; r++)
                #pragma unroll
                for (int c = 0; c < 4; c++) acc[r][c] = fmaf(a[r], b[c], acc[r][c]);
        }
    }

    #pragma unroll
    for (int r = 0; r < 8; r++) {
        int grow = row0 + r0 + r;
        if (grow >= N_NODES) break;
        float4 gv = make_float4(acc[r][0], acc[r][1], acc[r][2], acc[r][3]);
        reinterpret_cast<float4*>(g_G + (size_t)grow * DOUT + c0)[0] = gv;
    }
}

// ---------------------------------------------------------------------------
extern "C" void kernel_launch(void* const* d_in, const int* in_sizes, int n_in,
                              void* d_out, int out_size) {
    const float* x  = (const float*)d_in[0];
    const int*   ei = (const int*)d_in[1];      // [2, E]
    const float* W1 = (const float*)d_in[2];
    const float* b1 = (const float*)d_in[3];
    const float* W2 = (const float*)d_in[4];
    const float* b2 = (const float*)d_in[5];
    float* out = (float*)d_out;

    const int* src = ei;
    const int* dst = ei + N_EDGES;

    // CSR build (reused by both layers) + dinv
    int* degi_ptr = nullptr;
    int* bsum_ptr = nullptr;
    cudaGetSymbolAddress((void**)&degi_ptr, g_degi);
    cudaGetSymbolAddress((void**)&bsum_ptr, g_bsum);
    cudaMemsetAsync(degi_ptr, 0, N_NODES * sizeof(int));
    cudaMemsetAsync(bsum_ptr, 0xFF, SCAN_NB * sizeof(int));   // -1 sentinel

    k_count <<<(N_EDGES / 2 + 255) / 256, 256>>>(dst);
    k_scan  <<<SCAN_NB, SCAN_BS>>>();
    k_fill  <<<(N_EDGES / 2 + 255) / 256, 256>>>(src, dst);

    // layer 1: pull-aggregate x, then GEMM (+bias+relu fused)
    k_aggX  <<<(N_NODES + 7) / 8, 256>>>(x);
    k_gemm1 <<<(N_NODES + 127) / 128, 256>>>(W1, b1);

    // layer 2: GEMM (128 -> 64), then pull-aggregate into out (+bias fused)
    k_gemm2 <<<(N_NODES + 127) / 128, 256>>>(W2);
    k_agg2  <<<(N_NODES + 7) / 8, 256>>>(b2, out);
}